// round 5
// baseline (speedup 1.0000x reference)
#include <cuda_runtime.h>

// C[b,g] = softor_s( softand_l( x[b, I[g,s,l]] ) ),  gamma = 1e-3
// B=64, G=2048, S=32, L=8

#define NB 64
#define NG 2048
#define NS 32
#define NL 8
#define NCHUNK 8              // s-dimension split across 8 warps
#define SPER (NS / NCHUNK)    // 4 s-values per chunk
#define NTHR (NCHUNK * 32)    // 256 threads

// 1/(gamma*ln2) and gamma*ln2
#define KINV 1442.6950408889634f
#define GLN2 0.0006931471805599453f
// KINV * 2^23 (Schraudolph scale) and 127<<23 as float
#define EXP2C 12102202671104.0f
#define MAGICF 1065353216.0f

// Transposed x: xT[g][b] -> warp lanes (float2 each) -> coalesced gathers.
__device__ float g_xT[NG * NB];

// Tiled transpose: 64x2048 -> 2048x64, coalesced both sides.
__global__ void transpose_kernel(const float* __restrict__ x) {
    __shared__ float tile[32][33];
    const int gx = blockIdx.x * 32;
    const int bx = blockIdx.y * 32;
    const int tx = threadIdx.x;
    const int ty = threadIdx.y;
#pragma unroll
    for (int i = 0; i < 32; i += 8)
        tile[ty + i][tx] = x[(bx + ty + i) * NG + gx + tx];
    __syncthreads();
#pragma unroll
    for (int i = 0; i < 32; i += 8)
        g_xT[(gx + ty + i) * NB + bx + tx] = tile[tx][ty + i];
}

__device__ __forceinline__ float ex2_approx(float t) {
    float r;
    asm("ex2.approx.ftz.f32 %0, %1;" : "=f"(r) : "f"(t));
    return r;
}
__device__ __forceinline__ float lg2_approx(float t) {
    float r;
    asm("lg2.approx.f32 %0, %1;" : "=f"(r) : "f"(t));
    return r;
}

// Fast exp2 for t = d*KINV, d <= 0, via float bit pattern. Exact at d == 0.
// F2I saturates (defined in PTX); imax clamps the underflow region to +0.
__device__ __forceinline__ float exp2_fast(float d) {
    float y = fmaf(d, EXP2C, MAGICF);
    int i = __float2int_rn(y);
    i = max(i, 0);
    return __int_as_float(i);
}

// One block (256 threads) per g:
//   warp w handles s in [w*4, w*4+4); lane covers b = 2*lane, 2*lane+1 (float2).
__global__ __launch_bounds__(NTHR, 8) void clause_kernel(
    const int* __restrict__ I,  // [NG, NS, NL] int32
    float* __restrict__ out)    // [NB, NG]
{
    const int g = blockIdx.x;
    const int tid = threadIdx.x;
    const int lane = tid & 31;
    const int chunk = tid >> 5;

    __shared__ int sidx[NS * NL];
    __shared__ float pM[NCHUNK][NB];
    __shared__ float pS[NCHUNK][NB];

    if (tid < NS * NL / 4) {
        ((int4*)sidx)[tid] = ((const int4*)(I + g * (NS * NL)))[tid];
    }
    __syncthreads();

    const float2* __restrict__ xT2 = (const float2*)(g_xT);  // row stride NB/2
    const int4* __restrict__ sidx4 = (const int4*)sidx;

    float ax[SPER], ay[SPER];

#pragma unroll
    for (int si = 0; si < SPER; si++) {
        const int s = chunk * SPER + si;
        const int4 i0 = sidx4[s * 2 + 0];
        const int4 i1 = sidx4[s * 2 + 1];

        float2 v0 = xT2[(i0.x & (NG - 1)) * (NB / 2) + lane];
        float2 v1 = xT2[(i0.y & (NG - 1)) * (NB / 2) + lane];
        float2 v2 = xT2[(i0.z & (NG - 1)) * (NB / 2) + lane];
        float2 v3 = xT2[(i0.w & (NG - 1)) * (NB / 2) + lane];
        float2 v4 = xT2[(i1.x & (NG - 1)) * (NB / 2) + lane];
        float2 v5 = xT2[(i1.y & (NG - 1)) * (NB / 2) + lane];
        float2 v6 = xT2[(i1.z & (NG - 1)) * (NB / 2) + lane];
        float2 v7 = xT2[(i1.w & (NG - 1)) * (NB / 2) + lane];

        float mx = fminf(fminf(fminf(v0.x, v1.x), fminf(v2.x, v3.x)),
                         fminf(fminf(v4.x, v5.x), fminf(v6.x, v7.x)));
        float my = fminf(fminf(fminf(v0.y, v1.y), fminf(v2.y, v3.y)),
                         fminf(fminf(v4.y, v5.y), fminf(v6.y, v7.y)));

        float sx = exp2_fast(mx - v0.x) + exp2_fast(mx - v1.x)
                 + exp2_fast(mx - v2.x) + exp2_fast(mx - v3.x)
                 + exp2_fast(mx - v4.x) + exp2_fast(mx - v5.x)
                 + exp2_fast(mx - v6.x) + exp2_fast(mx - v7.x);
        float sy = exp2_fast(my - v0.y) + exp2_fast(my - v1.y)
                 + exp2_fast(my - v2.y) + exp2_fast(my - v3.y)
                 + exp2_fast(my - v4.y) + exp2_fast(my - v5.y)
                 + exp2_fast(my - v6.y) + exp2_fast(my - v7.y);

        ax[si] = mx - GLN2 * lg2_approx(sx);
        ay[si] = my - GLN2 * lg2_approx(sy);
    }

    // Partial softor over this chunk's SPER s-values (exact MUFU path — cheap).
    float Mx = ax[0], My = ay[0];
#pragma unroll
    for (int si = 1; si < SPER; si++) {
        Mx = fmaxf(Mx, ax[si]);
        My = fmaxf(My, ay[si]);
    }
    float Sx = 0.0f, Sy = 0.0f;
#pragma unroll
    for (int si = 0; si < SPER; si++) {
        Sx += ex2_approx((ax[si] - Mx) * KINV);
        Sy += ex2_approx((ay[si] - My) * KINV);
    }

    const int b0 = lane * 2;
    pM[chunk][b0] = Mx;  pM[chunk][b0 + 1] = My;
    pS[chunk][b0] = Sx;  pS[chunk][b0 + 1] = Sy;
    __syncthreads();

    // First 64 threads: merge NCHUNK partial (M, S) pairs per b and write out.
    if (tid < NB) {
        const int b = tid;
        float M = pM[0][b];
#pragma unroll
        for (int c = 1; c < NCHUNK; c++) M = fmaxf(M, pM[c][b]);
        float S = 0.0f;
#pragma unroll
        for (int c = 0; c < NCHUNK; c++)
            S += pS[c][b] * ex2_approx((pM[c][b] - M) * KINV);
        out[b * NG + g] = M + GLN2 * lg2_approx(S);
    }
}

extern "C" void kernel_launch(void* const* d_in, const int* in_sizes, int n_in,
                              void* d_out, int out_size) {
    // Identify inputs by element count:
    //   x:  64*2048   = 131072 float32
    //   I:  2048*32*8 = 524288 int32
    const float* x = nullptr;
    const int* I = nullptr;
    for (int i = 0; i < n_in; i++) {
        if (in_sizes[i] == NB * NG)           x = (const float*)d_in[i];
        else if (in_sizes[i] == NG * NS * NL) I = (const int*)d_in[i];
    }

    float* out = (float*)d_out;  // [64, 2048] fp32

    dim3 tgrid(NG / 32, NB / 32);
    dim3 tblock(32, 8);
    transpose_kernel<<<tgrid, tblock>>>(x);
    clause_kernel<<<NG, NTHR>>>(I, out);
}

// round 6
// speedup vs baseline: 1.9388x; 1.9388x over previous
#include <cuda_runtime.h>

// C[b,g] = softor_s( softand_l( x[b, I[g,s,l]] ) ),  gamma = 1e-3
// B=64, G=2048, S=32, L=8
//
// Scaled domain: w = -x * KINV  (KINV = 1/(gamma*ln2))
//   softand':  mW = max_l w,  sum = sum_l exp2(w_l - mW),  aw = mW + lg2(sum)
//              (aw = -softand * KINV)
//   softor' :  Mw = min_s aw,  S = sum_s exp2(Mw - aw_s)
//              C  = (lg2(S) - Mw) * gamma*ln2
// gamma*ln2 * KINV == 1 exactly cancels all per-term scaling.

#define NB 64
#define NG 2048
#define NS 32
#define NL 8
#define NCHUNK 8              // s-dimension split across 8 warps
#define SPER (NS / NCHUNK)    // 4 s-values per chunk
#define NTHR (NCHUNK * 32)    // 256 threads

#define KINV 1442.6950408889634f
#define GLN2 0.0006931471805599453f

// Transposed, negated, scaled x: w[g][b] = -x[b][g] * KINV.
__device__ float g_w[NG * NB];

// Tiled transpose 64x2048 -> 2048x64, coalesced both sides; fuses -x*KINV.
__global__ void transpose_kernel(const float* __restrict__ x) {
    __shared__ float tile[32][33];
    const int gx = blockIdx.x * 32;
    const int bx = blockIdx.y * 32;
    const int tx = threadIdx.x;
    const int ty = threadIdx.y;
#pragma unroll
    for (int i = 0; i < 32; i += 8)
        tile[ty + i][tx] = x[(bx + ty + i) * NG + gx + tx] * (-KINV);
    __syncthreads();
#pragma unroll
    for (int i = 0; i < 32; i += 8)
        g_w[(gx + ty + i) * NB + bx + tx] = tile[tx][ty + i];
}

__device__ __forceinline__ float ex2_approx(float t) {
    float r;
    asm("ex2.approx.ftz.f32 %0, %1;" : "=f"(r) : "f"(t));
    return r;
}
__device__ __forceinline__ float lg2_approx(float t) {
    float r;
    asm("lg2.approx.f32 %0, %1;" : "=f"(r) : "f"(t));
    return r;
}

// One block (256 threads) per g:
//   warp w handles s in [w*4, w*4+4); lane covers b = 2*lane, 2*lane+1 (float2).
__global__ __launch_bounds__(NTHR) void clause_kernel(
    const int* __restrict__ I,  // [NG, NS, NL] int32
    float* __restrict__ out)    // [NB, NG]
{
    const int g = blockIdx.x;
    const int tid = threadIdx.x;
    const int lane = tid & 31;
    const int chunk = tid >> 5;

    __shared__ int soff[NS * NL];          // pre-shifted byte offsets
    __shared__ float2 pM2[NCHUNK][NB / 2]; // partial min(aw) per chunk
    __shared__ float2 pS2[NCHUNK][NB / 2]; // partial sum-of-exp per chunk

    if (tid < NS * NL / 4) {
        int4 r = ((const int4*)(I + g * (NS * NL)))[tid];
        r.x = (r.x & (NG - 1)) << 8;   // *256 bytes = *(NB/2) float2
        r.y = (r.y & (NG - 1)) << 8;
        r.z = (r.z & (NG - 1)) << 8;
        r.w = (r.w & (NG - 1)) << 8;
        ((int4*)soff)[tid] = r;
    }
    __syncthreads();

    const char* lanebase = (const char*)g_w + lane * sizeof(float2);
    const int4* __restrict__ soff4 = (const int4*)soff;

    float awx[SPER], awy[SPER];

#pragma unroll
    for (int si = 0; si < SPER; si++) {
        const int s = chunk * SPER + si;
        const int4 o0 = soff4[s * 2 + 0];
        const int4 o1 = soff4[s * 2 + 1];

        float2 w0 = *(const float2*)(lanebase + o0.x);
        float2 w1 = *(const float2*)(lanebase + o0.y);
        float2 w2 = *(const float2*)(lanebase + o0.z);
        float2 w3 = *(const float2*)(lanebase + o0.w);
        float2 w4 = *(const float2*)(lanebase + o1.x);
        float2 w5 = *(const float2*)(lanebase + o1.y);
        float2 w6 = *(const float2*)(lanebase + o1.z);
        float2 w7 = *(const float2*)(lanebase + o1.w);

        float mx = fmaxf(fmaxf(fmaxf(w0.x, w1.x), fmaxf(w2.x, w3.x)),
                         fmaxf(fmaxf(w4.x, w5.x), fmaxf(w6.x, w7.x)));
        float my = fmaxf(fmaxf(fmaxf(w0.y, w1.y), fmaxf(w2.y, w3.y)),
                         fmaxf(fmaxf(w4.y, w5.y), fmaxf(w6.y, w7.y)));

        float sx = ex2_approx(w0.x - mx) + ex2_approx(w1.x - mx)
                 + ex2_approx(w2.x - mx) + ex2_approx(w3.x - mx)
                 + ex2_approx(w4.x - mx) + ex2_approx(w5.x - mx)
                 + ex2_approx(w6.x - mx) + ex2_approx(w7.x - mx);
        float sy = ex2_approx(w0.y - my) + ex2_approx(w1.y - my)
                 + ex2_approx(w2.y - my) + ex2_approx(w3.y - my)
                 + ex2_approx(w4.y - my) + ex2_approx(w5.y - my)
                 + ex2_approx(w6.y - my) + ex2_approx(w7.y - my);

        awx[si] = mx + lg2_approx(sx);
        awy[si] = my + lg2_approx(sy);
    }

    // Partial softor over this chunk's SPER aw values (min in w-domain).
    float Mwx = awx[0], Mwy = awy[0];
#pragma unroll
    for (int si = 1; si < SPER; si++) {
        Mwx = fminf(Mwx, awx[si]);
        Mwy = fminf(Mwy, awy[si]);
    }
    float Sx = 0.0f, Sy = 0.0f;
#pragma unroll
    for (int si = 0; si < SPER; si++) {
        Sx += ex2_approx(Mwx - awx[si]);
        Sy += ex2_approx(Mwy - awy[si]);
    }

    pM2[chunk][lane] = make_float2(Mwx, Mwy);
    pS2[chunk][lane] = make_float2(Sx, Sy);
    __syncthreads();

    // First 64 threads: merge NCHUNK partials per b and write out.
    if (tid < NB) {
        const int b = tid;
        const float* pM = (const float*)pM2;  // [NCHUNK][NB]
        const float* pS = (const float*)pS2;
        float Mw = pM[b];
#pragma unroll
        for (int c = 1; c < NCHUNK; c++) Mw = fminf(Mw, pM[c * NB + b]);
        float S = 0.0f;
#pragma unroll
        for (int c = 0; c < NCHUNK; c++)
            S = fmaf(pS[c * NB + b], ex2_approx(Mw - pM[c * NB + b]), S);
        out[b * NG + g] = (lg2_approx(S) - Mw) * GLN2;
    }
}

extern "C" void kernel_launch(void* const* d_in, const int* in_sizes, int n_in,
                              void* d_out, int out_size) {
    // Identify inputs by element count:
    //   x:  64*2048   = 131072 float32
    //   I:  2048*32*8 = 524288 int32
    const float* x = nullptr;
    const int* I = nullptr;
    for (int i = 0; i < n_in; i++) {
        if (in_sizes[i] == NB * NG)           x = (const float*)d_in[i];
        else if (in_sizes[i] == NG * NS * NL) I = (const int*)d_in[i];
    }

    float* out = (float*)d_out;  // [64, 2048] fp32

    dim3 tgrid(NG / 32, NB / 32);
    dim3 tblock(32, 8);
    transpose_kernel<<<tgrid, tblock>>>(x);
    clause_kernel<<<NG, NTHR>>>(I, out);
}

// round 7
// speedup vs baseline: 1.9849x; 1.0238x over previous
#include <cuda_runtime.h>

// C[b,g] = softor_s( softand_l( x[b, I[g,s,l]] ) ),  gamma = 1e-3
// B=64, G=2048, S=32, L=8
//
// Scaled domain: w = -x * KINV  (KINV = 1/(gamma*ln2))
//   softand':  mW = max_l w,  sum = sum_l exp2(w_l - mW),  aw = mW + lg2(sum)
//   softor' :  Mw = min_s aw,  S = sum_s exp2(Mw - aw_s)
//              C  = (lg2(S) - Mw) * gamma*ln2

#define NB 64
#define NG 2048
#define NS 32
#define NL 8
#define NCHUNK 8              // s-dimension split across 8 warps
#define SPER (NS / NCHUNK)    // 4 s-values per chunk
#define NTHR (NCHUNK * 32)    // 256 threads

#define KINV 1442.6950408889634f
#define GLN2 0.0006931471805599453f

// Transposed, negated, scaled x: w[g][b] = -x[b][g] * KINV.
__device__ float g_w[NG * NB];

// Tiled transpose 64x2048 -> 2048x64, coalesced both sides; fuses -x*KINV.
__global__ void transpose_kernel(const float* __restrict__ x) {
#if __CUDA_ARCH__ >= 900
    // Allow the dependent clause_kernel to start its prologue immediately.
    cudaTriggerProgrammaticLaunchCompletion();
#endif
    __shared__ float tile[32][33];
    const int gx = blockIdx.x * 32;
    const int bx = blockIdx.y * 32;
    const int tx = threadIdx.x;
    const int ty = threadIdx.y;
#pragma unroll
    for (int i = 0; i < 32; i += 8)
        tile[ty + i][tx] = x[(bx + ty + i) * NG + gx + tx] * (-KINV);
    __syncthreads();
#pragma unroll
    for (int i = 0; i < 32; i += 8)
        g_w[(gx + ty + i) * NB + bx + tx] = tile[tx][ty + i];
}

__device__ __forceinline__ float ex2_approx(float t) {
    float r;
    asm("ex2.approx.ftz.f32 %0, %1;" : "=f"(r) : "f"(t));
    return r;
}
__device__ __forceinline__ float lg2_approx(float t) {
    float r;
    asm("lg2.approx.f32 %0, %1;" : "=f"(r) : "f"(t));
    return r;
}

// One block (256 threads) per g:
//   warp w handles s in [w*4, w*4+4); lane covers b = 2*lane, 2*lane+1 (float2).
__global__ __launch_bounds__(NTHR) void clause_kernel(
    const int* __restrict__ I,  // [NG, NS, NL] int32
    float* __restrict__ out)    // [NB, NG]
{
    const int g = blockIdx.x;
    const int tid = threadIdx.x;
    const int lane = tid & 31;
    const int chunk = tid >> 5;

    __shared__ int soff[NS * NL];          // pre-shifted byte offsets
    __shared__ float2 pM2[NCHUNK][NB / 2]; // partial min(aw) per chunk
    __shared__ float2 pS2[NCHUNK][NB / 2]; // partial sum-of-exp per chunk

    // Prologue: independent of g_w — runs concurrently with the transpose.
    if (tid < NS * NL / 4) {
        int4 r = ((const int4*)(I + g * (NS * NL)))[tid];
        r.x = (r.x & (NG - 1)) << 8;   // *256 bytes = row stride in bytes
        r.y = (r.y & (NG - 1)) << 8;
        r.z = (r.z & (NG - 1)) << 8;
        r.w = (r.w & (NG - 1)) << 8;
        ((int4*)soff)[tid] = r;
    }
    __syncthreads();

#if __CUDA_ARCH__ >= 900
    // g_w produced by transpose_kernel — wait for primary completion.
    cudaGridDependencySynchronize();
#endif

    const char* lanebase = (const char*)g_w + lane * sizeof(float2);
    const int4* __restrict__ soff4 = (const int4*)soff;

    float awx[SPER], awy[SPER];

#pragma unroll
    for (int si = 0; si < SPER; si++) {
        const int s = chunk * SPER + si;
        const int4 o0 = soff4[s * 2 + 0];
        const int4 o1 = soff4[s * 2 + 1];

        float2 w0 = *(const float2*)(lanebase + o0.x);
        float2 w1 = *(const float2*)(lanebase + o0.y);
        float2 w2 = *(const float2*)(lanebase + o0.z);
        float2 w3 = *(const float2*)(lanebase + o0.w);
        float2 w4 = *(const float2*)(lanebase + o1.x);
        float2 w5 = *(const float2*)(lanebase + o1.y);
        float2 w6 = *(const float2*)(lanebase + o1.z);
        float2 w7 = *(const float2*)(lanebase + o1.w);

        float mx = fmaxf(fmaxf(fmaxf(w0.x, w1.x), fmaxf(w2.x, w3.x)),
                         fmaxf(fmaxf(w4.x, w5.x), fmaxf(w6.x, w7.x)));
        float my = fmaxf(fmaxf(fmaxf(w0.y, w1.y), fmaxf(w2.y, w3.y)),
                         fmaxf(fmaxf(w4.y, w5.y), fmaxf(w6.y, w7.y)));

        // Balanced (depth-3) sum trees for shorter dependency chains.
        float ex0 = ex2_approx(w0.x - mx), ex1 = ex2_approx(w1.x - mx);
        float ex2_ = ex2_approx(w2.x - mx), ex3 = ex2_approx(w3.x - mx);
        float ex4 = ex2_approx(w4.x - mx), ex5 = ex2_approx(w5.x - mx);
        float ex6 = ex2_approx(w6.x - mx), ex7 = ex2_approx(w7.x - mx);
        float sx = ((ex0 + ex1) + (ex2_ + ex3)) + ((ex4 + ex5) + (ex6 + ex7));

        float ey0 = ex2_approx(w0.y - my), ey1 = ex2_approx(w1.y - my);
        float ey2 = ex2_approx(w2.y - my), ey3 = ex2_approx(w3.y - my);
        float ey4 = ex2_approx(w4.y - my), ey5 = ex2_approx(w5.y - my);
        float ey6 = ex2_approx(w6.y - my), ey7 = ex2_approx(w7.y - my);
        float sy = ((ey0 + ey1) + (ey2 + ey3)) + ((ey4 + ey5) + (ey6 + ey7));

        awx[si] = mx + lg2_approx(sx);
        awy[si] = my + lg2_approx(sy);
    }

    // Partial softor over this chunk's SPER aw values (min in w-domain).
    float Mwx = fminf(fminf(awx[0], awx[1]), fminf(awx[2], awx[3]));
    float Mwy = fminf(fminf(awy[0], awy[1]), fminf(awy[2], awy[3]));
    float Sx = (ex2_approx(Mwx - awx[0]) + ex2_approx(Mwx - awx[1]))
             + (ex2_approx(Mwx - awx[2]) + ex2_approx(Mwx - awx[3]));
    float Sy = (ex2_approx(Mwy - awy[0]) + ex2_approx(Mwy - awy[1]))
             + (ex2_approx(Mwy - awy[2]) + ex2_approx(Mwy - awy[3]));

    pM2[chunk][lane] = make_float2(Mwx, Mwy);
    pS2[chunk][lane] = make_float2(Sx, Sy);
    __syncthreads();

    // First 64 threads: merge NCHUNK partials per b and write out.
    if (tid < NB) {
        const int b = tid;
        const float* pM = (const float*)pM2;  // [NCHUNK][NB]
        const float* pS = (const float*)pS2;
        float Mw = pM[b];
#pragma unroll
        for (int c = 1; c < NCHUNK; c++) Mw = fminf(Mw, pM[c * NB + b]);
        float S = 0.0f;
#pragma unroll
        for (int c = 0; c < NCHUNK; c++)
            S = fmaf(pS[c * NB + b], ex2_approx(Mw - pM[c * NB + b]), S);
        out[b * NG + g] = (lg2_approx(S) - Mw) * GLN2;
    }
}

extern "C" void kernel_launch(void* const* d_in, const int* in_sizes, int n_in,
                              void* d_out, int out_size) {
    // Identify inputs by element count:
    //   x:  64*2048   = 131072 float32
    //   I:  2048*32*8 = 524288 int32
    const float* x = nullptr;
    const int* I = nullptr;
    for (int i = 0; i < n_in; i++) {
        if (in_sizes[i] == NB * NG)           x = (const float*)d_in[i];
        else if (in_sizes[i] == NG * NS * NL) I = (const int*)d_in[i];
    }

    float* out = (float*)d_out;  // [64, 2048] fp32

    dim3 tgrid(NG / 32, NB / 32);
    dim3 tblock(32, 8);
    transpose_kernel<<<tgrid, tblock>>>(x);

    // PDL: clause_kernel may launch early; it gates on transpose completion
    // via cudaGridDependencySynchronize() before touching g_w.
    cudaLaunchConfig_t cfg = {};
    cfg.gridDim = dim3(NG);
    cfg.blockDim = dim3(NTHR);
    cfg.dynamicSmemBytes = 0;
    cfg.stream = 0;  // same (legacy default) stream the harness captures
    cudaLaunchAttribute attr[1];
    attr[0].id = cudaLaunchAttributeProgrammaticStreamSerialization;
    attr[0].val.programmaticStreamSerializationAllowed = 1;
    cfg.attrs = attr;
    cfg.numAttrs = 1;
    cudaLaunchKernelEx(&cfg, clause_kernel, I, (float*)d_out);
}